// round 11
// baseline (speedup 1.0000x reference)
#include <cuda_runtime.h>
#include <cuda_bf16.h>
#include <float.h>
#include <stdint.h>

// Problem constants
#define BB     2
#define SS     2048
#define DD     2048
#define HH     16
#define HDIM   128
#define WINDOW 256
#define MROWS  (BB * SS)   // 4096
#define MD     ((long)MROWS * DD)

// ---------------------------------------------------------------------------
// Scratch (device globals — no allocation allowed)
// ---------------------------------------------------------------------------
__device__ float g_qkv[3 * MROWS * DD];       // q | k | v
__device__ float g_ao [MROWS * DD];           // rna(hs) first, then attn output
__device__ __nv_bfloat16 g_ahi[MROWS * DD];
__device__ __nv_bfloat16 g_alo[MROWS * DD];
__device__ __nv_bfloat16 g_whi[2 * DD * DD];  // Wq | Wk  (bf16 hi)
__device__ __nv_bfloat16 g_wlo[2 * DD * DD];  // Wq | Wk  (bf16 lo)
__device__ float g_wT[2 * DD * DD];           // WvT | WoT (tf32-rounded fp32)

// ---------------------------------------------------------------------------
// PTX helpers (family-wide only: harness emits compute_103 PTX -> no tcgen05)
// ---------------------------------------------------------------------------
__device__ __forceinline__ uint32_t smem_u32(const void* p) {
    uint32_t a;
    asm("{ .reg .u64 t; cvta.to.shared.u64 t, %1; cvt.u32.u64 %0, t; }"
        : "=r"(a) : "l"(p));
    return a;
}

__device__ __forceinline__ float rna_tf32(float x) {
    float y;
    asm("cvt.rna.tf32.f32 %0, %1;" : "=f"(y) : "f"(x));
    return y;
}

#define CP16(dst, src) \
    asm volatile("cp.async.cg.shared.global [%0], [%1], 16;" :: "r"(dst), "l"(src))
#define CP_COMMIT() asm volatile("cp.async.commit_group;" ::: "memory")
#define CP_WAIT1()  asm volatile("cp.async.wait_group 1;" ::: "memory")
#define CP_WAIT0()  asm volatile("cp.async.wait_group 0;" ::: "memory")

#define LDSM_X4(r0, r1, r2, r3, addr) \
    asm volatile("ldmatrix.sync.aligned.m8n8.x4.shared.b16 {%0,%1,%2,%3}, [%4];" \
        : "=r"(r0), "=r"(r1), "=r"(r2), "=r"(r3) : "r"(addr))

#define MMA16816(d, a, b) \
    asm volatile("mma.sync.aligned.m16n8k16.row.col.f32.bf16.bf16.f32 " \
        "{%0,%1,%2,%3}, {%4,%5,%6,%7}, {%8,%9}, {%0,%1,%2,%3};" \
        : "+f"((d)[0]), "+f"((d)[1]), "+f"((d)[2]), "+f"((d)[3]) \
        : "r"((a)[0]), "r"((a)[1]), "r"((a)[2]), "r"((a)[3]), \
          "r"((b)[0]), "r"((b)[1]))

#define MMA_TF32(d, a, b) \
    asm volatile("mma.sync.aligned.m16n8k8.row.col.f32.tf32.tf32.f32 " \
        "{%0,%1,%2,%3}, {%4,%5,%6,%7}, {%8,%9}, {%0,%1,%2,%3};" \
        : "+f"((d)[0]), "+f"((d)[1]), "+f"((d)[2]), "+f"((d)[3]) \
        : "r"((a)[0]), "r"((a)[1]), "r"((a)[2]), "r"((a)[3]), \
          "r"((b)[0]), "r"((b)[1]))

// ---------------------------------------------------------------------------
// Split fp32 -> bf16 hi + lo AND tf32-rounded fp32 copy (for the tf32 V gemm)
// ---------------------------------------------------------------------------
__global__ __launch_bounds__(256) void split3_kernel(
    const float* __restrict__ X, __nv_bfloat16* __restrict__ H,
    __nv_bfloat16* __restrict__ L, float* __restrict__ R, int n4)
{
    int i = blockIdx.x * blockDim.x + threadIdx.x;
    if (i >= n4) return;
    float4 x = ((const float4*)X)[i];
    __nv_bfloat16 h0 = __float2bfloat16(x.x);
    __nv_bfloat16 h1 = __float2bfloat16(x.y);
    __nv_bfloat16 h2 = __float2bfloat16(x.z);
    __nv_bfloat16 h3 = __float2bfloat16(x.w);
    __nv_bfloat16 l0 = __float2bfloat16(x.x - __bfloat162float(h0));
    __nv_bfloat16 l1 = __float2bfloat16(x.y - __bfloat162float(h1));
    __nv_bfloat16 l2 = __float2bfloat16(x.z - __bfloat162float(h2));
    __nv_bfloat16 l3 = __float2bfloat16(x.w - __bfloat162float(h3));
    ((__nv_bfloat162*)H)[2*i]   = __nv_bfloat162(h0, h1);
    ((__nv_bfloat162*)H)[2*i+1] = __nv_bfloat162(h2, h3);
    ((__nv_bfloat162*)L)[2*i]   = __nv_bfloat162(l0, l1);
    ((__nv_bfloat162*)L)[2*i+1] = __nv_bfloat162(l2, l3);
    float4 r = make_float4(rna_tf32(x.x), rna_tf32(x.y),
                           rna_tf32(x.z), rna_tf32(x.w));
    ((float4*)R)[i] = r;
}

// ---------------------------------------------------------------------------
// W [K][N] fp32 -> transposed + bf16 split: TH/TL [N][K].  z picks matrix+slot.
// ---------------------------------------------------------------------------
__global__ __launch_bounds__(256) void wsplit3_kernel(
    const float* __restrict__ W0, const float* __restrict__ W1,
    const float* __restrict__ W2,
    __nv_bfloat16* __restrict__ TH, __nv_bfloat16* __restrict__ TL)
{
    __shared__ float t[32][33];
    const float* W = (blockIdx.z == 0) ? W0 : (blockIdx.z == 1) ? W1 : W2;
    __nv_bfloat16* th = TH + (long)blockIdx.z * DD * DD;
    __nv_bfloat16* tl = TL + (long)blockIdx.z * DD * DD;
    const int n0 = blockIdx.x * 32, k0 = blockIdx.y * 32;
    const int tx = threadIdx.x & 31, ty = threadIdx.x >> 5;
    #pragma unroll
    for (int i = 0; i < 32; i += 8)
        t[ty + i][tx] = W[(long)(k0 + ty + i) * DD + n0 + tx];
    __syncthreads();
    #pragma unroll
    for (int i = 0; i < 32; i += 8) {
        float x = t[tx][ty + i];
        long o = (long)(n0 + ty + i) * DD + k0 + tx;
        __nv_bfloat16 h = __float2bfloat16(x);
        th[o] = h;
        tl[o] = __float2bfloat16(x - __bfloat162float(h));
    }
}

// ---------------------------------------------------------------------------
// W [K][N] fp32 -> transposed + tf32-rounded fp32: T [N][K].  z picks matrix.
// ---------------------------------------------------------------------------
__global__ __launch_bounds__(256) void wT32_kernel(
    const float* __restrict__ W0, const float* __restrict__ W1,
    float* __restrict__ T)
{
    __shared__ float t[32][33];
    const float* W = blockIdx.z ? W1 : W0;
    float* out = T + (long)blockIdx.z * DD * DD;
    const int n0 = blockIdx.x * 32, k0 = blockIdx.y * 32;
    const int tx = threadIdx.x & 31, ty = threadIdx.x >> 5;
    #pragma unroll
    for (int i = 0; i < 32; i += 8)
        t[ty + i][tx] = W[(long)(k0 + ty + i) * DD + n0 + tx];
    __syncthreads();
    #pragma unroll
    for (int i = 0; i < 32; i += 8)
        out[(long)(n0 + ty + i) * DD + k0 + tx] = rna_tf32(t[tx][ty + i]);
}

// ---------------------------------------------------------------------------
// bf16x3 HMMA GEMM, packed-N weights (verified config: 3-stage, 2 CTAs/SM).
// ---------------------------------------------------------------------------
#define GKB      64
#define GNIT     96
#define GPAD     72
#define G_OPB    (128 * GPAD * 2)
#define G_STAGEB (2 * G_OPB)
#define GSMEM_TOTAL (3 * G_STAGEB)        // 110592 B

__device__ __forceinline__ void g_load_stage(
    uint32_t sbase, int stage, int tid,
    const __nv_bfloat16* __restrict__ Asrc, const __nv_bfloat16* __restrict__ Bsrc,
    long row0, long bcol0, int kc)
{
    const uint32_t abase = sbase + stage * G_STAGEB;
    const uint32_t bbase = abase + G_OPB;
    const __nv_bfloat16* Ap = Asrc + row0 * DD + kc;
    const __nv_bfloat16* Bp = Bsrc + bcol0 * DD + kc;
    #pragma unroll
    for (int i = 0; i < 4; i++) {
        int idx = i * 256 + tid;
        int r  = idx >> 3;
        int ch = idx & 7;
        uint32_t so = (uint32_t)(r * (GPAD * 2) + ch * 16);
        CP16(abase + so, Ap + (long)r * DD + ch * 8);
        CP16(bbase + so, Bp + (long)r * DD + ch * 8);
    }
}

__global__ __launch_bounds__(256, 2) void gemm_bf16x3_kernel(
    const __nv_bfloat16* __restrict__ Ahi, const __nv_bfloat16* __restrict__ Alo,
    const __nv_bfloat16* __restrict__ Bhi, const __nv_bfloat16* __restrict__ Blo,
    const float* __restrict__ bias, float* __restrict__ Cbase)
{
    extern __shared__ char gsm[];
    const uint32_t sb = smem_u32(gsm);
    const int tid  = threadIdx.x;
    const int wid  = tid >> 5;
    const int lane = tid & 31;
    const long bcol0 = (long)blockIdx.x * 128;
    const long row0  = (long)blockIdx.y * 128;
    const int  which = (int)(bcol0 >> 11);
    const long cc0   = bcol0 & 2047;
    float* C = Cbase + (long)which * MD;

    const int warp_m = (wid >> 1) * 32;
    const int warp_n = (wid & 1) * 64;
    const int lr = lane & 15;
    const int hl = lane >> 4;

    float acc[2][8][4];
    #pragma unroll
    for (int mt = 0; mt < 2; mt++)
        #pragma unroll
        for (int nt = 0; nt < 8; nt++)
            #pragma unroll
            for (int e = 0; e < 4; e++)
                acc[mt][nt][e] = 0.0f;

    g_load_stage(sb, 0, tid, Ahi, Bhi, row0, bcol0, 0);
    CP_COMMIT();
    g_load_stage(sb, 1, tid, Ahi, Bhi, row0, bcol0, GKB);
    CP_COMMIT();

    int s = 0, ps = 2;
    #pragma unroll 1
    for (int it = 0; it < GNIT; it++) {
        CP_WAIT1();
        __syncthreads();

        const int nit = it + 2;
        if (nit < GNIT) {
            const int pass = nit >> 5;
            const int kc = (nit & 31) * GKB;
            const __nv_bfloat16* As = (pass == 2) ? Alo : Ahi;
            const __nv_bfloat16* Bs = (pass == 1) ? Blo : Bhi;
            g_load_stage(sb, ps, tid, As, Bs, row0, bcol0, kc);
        }
        CP_COMMIT();

        const uint32_t sA = sb + s * G_STAGEB;
        const uint32_t sB = sA + G_OPB;
        #pragma unroll
        for (int ks = 0; ks < 4; ks++) {
            const int k0 = ks * 16;
            uint32_t aF[2][4], bF[8][2];
            #pragma unroll
            for (int mt = 0; mt < 2; mt++) {
                uint32_t addr = sA + (uint32_t)((warp_m + mt * 16 + lr) * (GPAD * 2)
                                              + (k0 + 8 * hl) * 2);
                LDSM_X4(aF[mt][0], aF[mt][1], aF[mt][2], aF[mt][3], addr);
            }
            #pragma unroll
            for (int nt2 = 0; nt2 < 4; nt2++) {
                uint32_t r0, r1, r2, r3;
                uint32_t addr = sB + (uint32_t)((warp_n + nt2 * 16 + lr) * (GPAD * 2)
                                              + (k0 + 8 * hl) * 2);
                LDSM_X4(r0, r1, r2, r3, addr);
                bF[2 * nt2][0]     = r0;
                bF[2 * nt2 + 1][0] = r1;
                bF[2 * nt2][1]     = r2;
                bF[2 * nt2 + 1][1] = r3;
            }
            #pragma unroll
            for (int mt = 0; mt < 2; mt++)
                #pragma unroll
                for (int nt = 0; nt < 8; nt++)
                    MMA16816(acc[mt][nt], aF[mt], bF[nt]);
        }
        s = (s == 2) ? 0 : s + 1;
        ps = (ps == 2) ? 0 : ps + 1;
    }

    const int erow = lane >> 2;
    const int ecol = (lane & 3) * 2;
    #pragma unroll
    for (int mt = 0; mt < 2; mt++) {
        #pragma unroll
        for (int nt = 0; nt < 8; nt++) {
            const long r  = row0 + warp_m + mt * 16 + erow;
            const long cc = cc0 + warp_n + nt * 8 + ecol;
            float b0 = bias ? bias[cc] : 0.0f;
            float b1 = bias ? bias[cc + 1] : 0.0f;
            float2 v0 = make_float2(acc[mt][nt][0] + b0, acc[mt][nt][1] + b1);
            float2 v1 = make_float2(acc[mt][nt][2] + b0, acc[mt][nt][3] + b1);
            *(float2*)(C + r * DD + cc)       = v0;
            *(float2*)(C + (r + 8) * DD + cc) = v1;
        }
    }
}

// ---------------------------------------------------------------------------
// Single-pass TF32 GEMM with ldmatrix fragments (verified round 10).
// ---------------------------------------------------------------------------
#define TKB   32
#define TNIT  64
#define TPAD  36
#define T_OPB (128 * TPAD * 4)
#define T_STAGEB (2 * T_OPB)
#define TSMEM_TOTAL (3 * T_STAGEB)        // 110592 B

__device__ __forceinline__ void t_load_stage(
    uint32_t sbase, int stage, int tid,
    const float* __restrict__ Asrc, const float* __restrict__ Bsrc,
    long row0, long col0, int kc)
{
    const uint32_t abase = sbase + stage * T_STAGEB;
    const uint32_t bbase = abase + T_OPB;
    const float* Ap = Asrc + row0 * DD + kc;
    const float* Bp = Bsrc + col0 * DD + kc;
    #pragma unroll
    for (int i = 0; i < 4; i++) {
        int idx = i * 256 + tid;
        int r  = idx >> 3;
        int ch = idx & 7;
        uint32_t so = (uint32_t)(r * (TPAD * 4) + ch * 16);
        CP16(abase + so, Ap + (long)r * DD + ch * 4);
        CP16(bbase + so, Bp + (long)r * DD + ch * 4);
    }
}

__global__ __launch_bounds__(256, 2) void gemm_tf32_kernel(
    const float* __restrict__ A, const float* __restrict__ Bt,
    const float* __restrict__ bias, float* __restrict__ C)
{
    extern __shared__ char tsm[];
    const uint32_t sb = smem_u32(tsm);
    const int tid  = threadIdx.x;
    const int wid  = tid >> 5;
    const int lane = tid & 31;
    const long col0 = (long)blockIdx.x * 128;
    const long row0 = (long)blockIdx.y * 128;

    const int warp_m = (wid >> 1) * 32;
    const int warp_n = (wid & 1) * 64;

    const int a_row = lane & 15;
    const int a_kof = (lane >> 4) * 4;
    const int b_row = (lane & 7) + ((lane >> 4) << 3);
    const int b_kof = ((lane >> 3) & 1) * 4;

    float acc[2][8][4];
    #pragma unroll
    for (int mt = 0; mt < 2; mt++)
        #pragma unroll
        for (int nt = 0; nt < 8; nt++)
            #pragma unroll
            for (int e = 0; e < 4; e++)
                acc[mt][nt][e] = 0.0f;

    t_load_stage(sb, 0, tid, A, Bt, row0, col0, 0);
    CP_COMMIT();
    t_load_stage(sb, 1, tid, A, Bt, row0, col0, TKB);
    CP_COMMIT();

    int s = 0, ps = 2;
    #pragma unroll 1
    for (int it = 0; it < TNIT; it++) {
        CP_WAIT1();
        __syncthreads();

        const int nit = it + 2;
        if (nit < TNIT)
            t_load_stage(sb, ps, tid, A, Bt, row0, col0, nit * TKB);
        CP_COMMIT();

        const uint32_t sA = sb + s * T_STAGEB;
        const uint32_t sB = sA + T_OPB;
        #pragma unroll
        for (int ks = 0; ks < 4; ks++) {
            const int k0 = ks * 8;
            uint32_t aF[2][4], bF[8][2];
            #pragma unroll
            for (int mt = 0; mt < 2; mt++) {
                uint32_t addr = sA + (uint32_t)((warp_m + mt * 16 + a_row) * (TPAD * 4)
                                              + (k0 + a_kof) * 4);
                LDSM_X4(aF[mt][0], aF[mt][1], aF[mt][2], aF[mt][3], addr);
            }
            #pragma unroll
            for (int nt2 = 0; nt2 < 4; nt2++) {
                uint32_t r0, r1, r2, r3;
                uint32_t addr = sB + (uint32_t)((warp_n + nt2 * 16 + b_row) * (TPAD * 4)
                                              + (k0 + b_kof) * 4);
                LDSM_X4(r0, r1, r2, r3, addr);
                bF[2 * nt2][0]     = r0;
                bF[2 * nt2][1]     = r1;
                bF[2 * nt2 + 1][0] = r2;
                bF[2 * nt2 + 1][1] = r3;
            }
            #pragma unroll
            for (int mt = 0; mt < 2; mt++)
                #pragma unroll
                for (int nt = 0; nt < 8; nt++)
                    MMA_TF32(acc[mt][nt], aF[mt], bF[nt]);
        }
        s = (s == 2) ? 0 : s + 1;
        ps = (ps == 2) ? 0 : ps + 1;
    }

    const int erow = lane >> 2;
    const int ecol = (lane & 3) * 2;
    #pragma unroll
    for (int mt = 0; mt < 2; mt++) {
        #pragma unroll
        for (int nt = 0; nt < 8; nt++) {
            const long r  = row0 + warp_m + mt * 16 + erow;
            const long cc = col0 + warp_n + nt * 8 + ecol;
            float b0 = bias ? bias[cc] : 0.0f;
            float b1 = bias ? bias[cc + 1] : 0.0f;
            float2 v0 = make_float2(acc[mt][nt][0] + b0, acc[mt][nt][1] + b1);
            float2 v1 = make_float2(acc[mt][nt][2] + b0, acc[mt][nt][3] + b1);
            *(float2*)(C + r * DD + cc)       = v0;
            *(float2*)(C + (r + 8) * DD + cc) = v1;
        }
    }
}

// ---------------------------------------------------------------------------
// Local-window attention — round-11 rewrite: cp.async everywhere, row-major
// operands (no scalar-STS transposes), double-buffered K/V with one-chunk
// prefetch hiding gmem latency behind the S/softmax/PV compute.
// Per iteration:  CP_WAIT0 -> __syncthreads (also ends prev PV -> buffer
// overwrite safe) -> issue next chunk's cp.async -> compute on current.
// SMEM (floats): Q[64][132] | K[2][64][132] | V[2][64][128] | PsT[64][64]
//   = 45824 floats = 183296 B (1 CTA/SM; latency now pipelined away).
// ---------------------------------------------------------------------------
#define BQ   64
#define BKC  64
#define AQP  132                           // Q/K row stride in floats (528 B)
#define ATT_SMEM_BYTES ((64*AQP + 2*64*AQP + 2*64*128 + 64*64) * 4)  // 183296

__device__ __forceinline__ void a_load_kv(
    uint32_t sb, int buf, int tid,
    const float* __restrict__ kptr, const float* __restrict__ vptr)
{
    const uint32_t kbase = sb + 64 * AQP * 4 + buf * (64 * AQP * 4);
    const uint32_t vbase = sb + 3 * 64 * AQP * 4 + buf * (64 * 128 * 4);
    #pragma unroll
    for (int i = 0; i < 8; i++) {
        int idx = i * 256 + tid;
        int row = idx >> 5;                // 0..63
        int ch  = idx & 31;                // 16B chunk in the 512B of row data
        CP16(kbase + (uint32_t)(row * (AQP * 4) + ch * 16),
             kptr + (long)row * DD + ch * 4);
        CP16(vbase + (uint32_t)(row * 512 + ch * 16),
             vptr + (long)row * DD + ch * 4);
    }
}

__global__ __launch_bounds__(256) void attn_local_kernel(
    const float* __restrict__ Q, const float* __restrict__ K,
    const float* __restrict__ V, const int* __restrict__ amask,
    float* __restrict__ O)
{
    const int q0 = blockIdx.x * BQ;
    const int h  = blockIdx.y;
    const int b  = blockIdx.z;

    extern __shared__ float sm[];
    const uint32_t sb = smem_u32(sm);
    float* Qs   = sm;                          // [64][132]
    float* Ksb_ = sm + 64 * AQP;               // [2][64][132]
    float* Vsb_ = sm + 3 * 64 * AQP;           // [2][64][128]
    float* PsT  = sm + 3 * 64 * AQP + 2 * 64 * 128;   // [64][64]

    const int tid = threadIdx.x;
    const int r   = tid >> 4;                  // q rows r*4..r*4+3
    const int c   = tid & 15;

    const int kb0 = (q0 >= WINDOW) ? (q0 - WINDOW) : 0;
    const int nch = (blockIdx.x + 1 < 5) ? (blockIdx.x + 1) : 5;

    // Prologue: Q + first K/V chunk, one cp.async group
    {
        const float* qptr = Q + ((long)(b * SS + q0)) * DD + h * HDIM;
        #pragma unroll
        for (int i = 0; i < 8; i++) {
            int idx = i * 256 + tid;
            int row = idx >> 5, ch = idx & 31;
            CP16(sb + (uint32_t)(row * (AQP * 4) + ch * 16),
                 qptr + (long)row * DD + ch * 4);
        }
        a_load_kv(sb, 0, tid,
                  K + ((long)(b * SS + kb0)) * DD + h * HDIM,
                  V + ((long)(b * SS + kb0)) * DD + h * HDIM);
        CP_COMMIT();
    }

    float m[4], l[4], o[4][8];
    #pragma unroll
    for (int i = 0; i < 4; i++) {
        m[i] = -FLT_MAX; l[i] = 0.0f;
        #pragma unroll
        for (int dd = 0; dd < 8; dd++) o[i][dd] = 0.0f;
    }

    #pragma unroll 1
    for (int ci = 0; ci < nch; ci++) {
        const int kb  = kb0 + ci * BKC;
        const int buf = ci & 1;
        float* Ks = Ksb_ + buf * (64 * AQP);
        float* Vs = Vsb_ + buf * (64 * 128);

        CP_WAIT0();          // current chunk (and Q on ci==0) landed
        __syncthreads();     // visible to all; also retires prev PV reads

        // Prefetch next chunk into the other buffer (prev PV done reading it)
        if (ci + 1 < nch) {
            const int kb2 = kb + BKC;
            a_load_kv(sb, buf ^ 1, tid,
                      K + ((long)(b * SS + kb2)) * DD + h * HDIM,
                      V + ((long)(b * SS + kb2)) * DD + h * HDIM);
        }
        CP_COMMIT();

        const int4 mk4 = *(const int4*)(amask + b * SS + kb + c * 4);

        // S = Q @ K^T (unscaled): row-major dot products
        float s[4][4];
        #pragma unroll
        for (int i = 0; i < 4; i++)
            #pragma unroll
            for (int j = 0; j < 4; j++) s[i][j] = 0.0f;

        #pragma unroll 2
        for (int d4 = 0; d4 < 32; d4++) {
            float4 q4[4], k4[4];
            #pragma unroll
            for (int i = 0; i < 4; i++)
                q4[i] = *(const float4*)&Qs[(r * 4 + i) * AQP + d4 * 4];
            #pragma unroll
            for (int j = 0; j < 4; j++)
                k4[j] = *(const float4*)&Ks[(c * 4 + j) * AQP + d4 * 4];
            #pragma unroll
            for (int i = 0; i < 4; i++)
                #pragma unroll
                for (int j = 0; j < 4; j++) {
                    float acc = s[i][j];
                    acc = fmaf(q4[i].x, k4[j].x, acc);
                    acc = fmaf(q4[i].y, k4[j].y, acc);
                    acc = fmaf(q4[i].z, k4[j].z, acc);
                    acc = fmaf(q4[i].w, k4[j].w, acc);
                    s[i][j] = acc;
                }
        }

        // Mask + online softmax
        const int mok[4] = {mk4.x, mk4.y, mk4.z, mk4.w};
        float scl[4];
        #pragma unroll
        for (int i = 0; i < 4; i++) {
            const int qi = q0 + r * 4 + i;
            #pragma unroll
            for (int j = 0; j < 4; j++) {
                const int kj = kb + c * 4 + j;
                bool ok = (kj <= qi) && (kj > qi - WINDOW) && (mok[j] > 0);
                if (!ok) s[i][j] = -FLT_MAX;
            }
            float mx = fmaxf(fmaxf(s[i][0], s[i][1]), fmaxf(s[i][2], s[i][3]));
            #pragma unroll
            for (int w = 1; w <= 8; w <<= 1)
                mx = fmaxf(mx, __shfl_xor_sync(0xffffffffu, mx, w));

            float mnew = fmaxf(m[i], mx);
            scl[i] = __expf(m[i] - mnew);
            m[i] = mnew;

            float sum = 0.0f;
            #pragma unroll
            for (int j = 0; j < 4; j++) {
                float p = (s[i][j] > -1e37f) ? __expf(s[i][j] - mnew) : 0.0f;
                s[i][j] = p;
                sum += p;
            }
            #pragma unroll
            for (int w = 1; w <= 8; w <<= 1)
                sum += __shfl_xor_sync(0xffffffffu, sum, w);

            l[i] = l[i] * scl[i] + sum;
            #pragma unroll
            for (int dd = 0; dd < 8; dd++) o[i][dd] *= scl[i];
        }

        // Stage P transposed + rotated (write conflicts ~2-way; reads broadcast)
        #pragma unroll
        for (int j = 0; j < 4; j++) {
            int row  = c * 4 + j;
            int wcol = (4 * r + 4 * c) & 63;
            *(float4*)&PsT[row * 64 + wcol] =
                make_float4(s[0][j], s[1][j], s[2][j], s[3][j]);
        }
        __syncthreads();

        // O += P @ V
        #pragma unroll 8
        for (int j = 0; j < BKC; j++) {
            int wcol = (4 * r + 4 * (j >> 2)) & 63;
            float4 p4 = *(const float4*)&PsT[j * 64 + wcol];
            float4 va = *(const float4*)&Vs[j * 128 + c * 8];
            float4 vb = *(const float4*)&Vs[j * 128 + c * 8 + 4];
            const float pv[4] = {p4.x, p4.y, p4.z, p4.w};
            const float vv[8] = {va.x, va.y, va.z, va.w, vb.x, vb.y, vb.z, vb.w};
            #pragma unroll
            for (int i = 0; i < 4; i++)
                #pragma unroll
                for (int dd = 0; dd < 8; dd++)
                    o[i][dd] = fmaf(pv[i], vv[dd], o[i][dd]);
        }
    }

    // Normalize + store (tf32-rounded for the Wo tf32 gemm)
    #pragma unroll
    for (int i = 0; i < 4; i++) {
        const int row = q0 + r * 4 + i;
        const float inv = 1.0f / l[i];
        const long base = ((long)(b * SS + row)) * DD + h * HDIM + c * 8;
        float out[8];
        #pragma unroll
        for (int dd = 0; dd < 8; dd++) out[dd] = rna_tf32(o[i][dd] * inv);
        *(float4*)(O + base)     = make_float4(out[0], out[1], out[2], out[3]);
        *(float4*)(O + base + 4) = make_float4(out[4], out[5], out[6], out[7]);
    }
}

// ---------------------------------------------------------------------------
// Launch
// ---------------------------------------------------------------------------
extern "C" void kernel_launch(void* const* d_in, const int* in_sizes, int n_in,
                              void* d_out, int out_size)
{
    const float* hs    = (const float*)d_in[0];
    const int*   amask = (const int*)  d_in[1];
    const float* Wq    = (const float*)d_in[2];
    const float* Wk    = (const float*)d_in[3];
    const float* Wv    = (const float*)d_in[4];
    const float* Wo    = (const float*)d_in[5];
    const float* bo    = (const float*)d_in[6];
    float*       out   = (float*)d_out;

    float *qkv, *ao, *wT;
    __nv_bfloat16 *ahi, *alo, *whi, *wlo;
    cudaGetSymbolAddress((void**)&qkv, g_qkv);
    cudaGetSymbolAddress((void**)&ao,  g_ao);
    cudaGetSymbolAddress((void**)&ahi, g_ahi);
    cudaGetSymbolAddress((void**)&alo, g_alo);
    cudaGetSymbolAddress((void**)&whi, g_whi);
    cudaGetSymbolAddress((void**)&wlo, g_wlo);
    cudaGetSymbolAddress((void**)&wT,  g_wT);

    cudaFuncSetAttribute(gemm_bf16x3_kernel,
                         cudaFuncAttributeMaxDynamicSharedMemorySize, GSMEM_TOTAL);
    cudaFuncSetAttribute(gemm_tf32_kernel,
                         cudaFuncAttributeMaxDynamicSharedMemorySize, TSMEM_TOTAL);
    cudaFuncSetAttribute(attn_local_kernel,
                         cudaFuncAttributeMaxDynamicSharedMemorySize, ATT_SMEM_BYTES);

    const int n4 = MROWS * DD / 4;

    // (1) hs -> bf16 hi/lo + tf32-rounded fp32 (in g_ao)
    split3_kernel<<<(n4 + 255) / 256, 256>>>(hs, ahi, alo, ao, n4);

    // (2) Wq/Wk -> bf16 transposed split
    dim3 wgrid2(DD / 32, DD / 32, 2);
    wsplit3_kernel<<<wgrid2, 256>>>(Wq, Wk, Wk, whi, wlo);

    // (3) Wv/Wo -> tf32-rounded fp32 transpose
    wT32_kernel<<<wgrid2, 256>>>(Wv, Wo, wT);

    // (4) V GEMM (single-pass tf32)
    dim3 tgrid(DD / 128, MROWS / 128);
    gemm_tf32_kernel<<<tgrid, 256, TSMEM_TOTAL>>>(ao, wT, nullptr, qkv + 2 * MD);

    // (5) fused QK GEMM (bf16x3)
    dim3 qkgrid(2 * DD / 128, MROWS / 128);
    gemm_bf16x3_kernel<<<qkgrid, 256, GSMEM_TOTAL>>>(ahi, alo, whi, wlo, nullptr, qkv);

    // (6) attention (cp.async pipelined): overwrites g_ao
    dim3 attn_grid(SS / BQ, HH, BB);
    attn_local_kernel<<<attn_grid, 256, ATT_SMEM_BYTES>>>(
        qkv, qkv + MD, qkv + 2 * MD, amask, ao);

    // (7) output projection (single-pass tf32)
    gemm_tf32_kernel<<<tgrid, 256, TSMEM_TOTAL>>>(ao, wT + (long)DD * DD, bo, out);
}

// round 12
// speedup vs baseline: 1.0282x; 1.0282x over previous
#include <cuda_runtime.h>
#include <cuda_bf16.h>
#include <float.h>
#include <stdint.h>

// Problem constants
#define BB     2
#define SS     2048
#define DD     2048
#define HH     16
#define HDIM   128
#define WINDOW 256
#define MROWS  (BB * SS)   // 4096
#define MD     ((long)MROWS * DD)

// ---------------------------------------------------------------------------
// Scratch (device globals — no allocation allowed)
// ---------------------------------------------------------------------------
__device__ float g_qkv[3 * MROWS * DD];       // q | k | v
__device__ float g_ao [MROWS * DD];           // rna(hs) first, then attn output
__device__ __nv_bfloat16 g_ahi[MROWS * DD];
__device__ __nv_bfloat16 g_alo[MROWS * DD];
__device__ __nv_bfloat16 g_whi[2 * DD * DD];  // Wq | Wk  (bf16 hi)
__device__ __nv_bfloat16 g_wlo[2 * DD * DD];  // Wq | Wk  (bf16 lo)
__device__ float g_wT[2 * DD * DD];           // WvT | WoT (tf32-rounded fp32)

// ---------------------------------------------------------------------------
// PTX helpers (family-wide only: harness emits compute_103 PTX -> no tcgen05)
// ---------------------------------------------------------------------------
__device__ __forceinline__ uint32_t smem_u32(const void* p) {
    uint32_t a;
    asm("{ .reg .u64 t; cvta.to.shared.u64 t, %1; cvt.u32.u64 %0, t; }"
        : "=r"(a) : "l"(p));
    return a;
}

__device__ __forceinline__ float rna_tf32(float x) {
    float y;
    asm("cvt.rna.tf32.f32 %0, %1;" : "=f"(y) : "f"(x));
    return y;
}

#define CP16(dst, src) \
    asm volatile("cp.async.cg.shared.global [%0], [%1], 16;" :: "r"(dst), "l"(src))
#define CP_COMMIT() asm volatile("cp.async.commit_group;" ::: "memory")
#define CP_WAIT1()  asm volatile("cp.async.wait_group 1;" ::: "memory")

#define LDSM_X4(r0, r1, r2, r3, addr) \
    asm volatile("ldmatrix.sync.aligned.m8n8.x4.shared.b16 {%0,%1,%2,%3}, [%4];" \
        : "=r"(r0), "=r"(r1), "=r"(r2), "=r"(r3) : "r"(addr))

#define MMA16816(d, a, b) \
    asm volatile("mma.sync.aligned.m16n8k16.row.col.f32.bf16.bf16.f32 " \
        "{%0,%1,%2,%3}, {%4,%5,%6,%7}, {%8,%9}, {%0,%1,%2,%3};" \
        : "+f"((d)[0]), "+f"((d)[1]), "+f"((d)[2]), "+f"((d)[3]) \
        : "r"((a)[0]), "r"((a)[1]), "r"((a)[2]), "r"((a)[3]), \
          "r"((b)[0]), "r"((b)[1]))

#define MMA_TF32(d, a, b) \
    asm volatile("mma.sync.aligned.m16n8k8.row.col.f32.tf32.tf32.f32 " \
        "{%0,%1,%2,%3}, {%4,%5,%6,%7}, {%8,%9}, {%0,%1,%2,%3};" \
        : "+f"((d)[0]), "+f"((d)[1]), "+f"((d)[2]), "+f"((d)[3]) \
        : "r"((a)[0]), "r"((a)[1]), "r"((a)[2]), "r"((a)[3]), \
          "r"((b)[0]), "r"((b)[1]))

// ---------------------------------------------------------------------------
// Split fp32 -> bf16 hi + lo AND tf32-rounded fp32 copy (for the tf32 V gemm)
// ---------------------------------------------------------------------------
__global__ __launch_bounds__(256) void split3_kernel(
    const float* __restrict__ X, __nv_bfloat16* __restrict__ H,
    __nv_bfloat16* __restrict__ L, float* __restrict__ R, int n4)
{
    int i = blockIdx.x * blockDim.x + threadIdx.x;
    if (i >= n4) return;
    float4 x = ((const float4*)X)[i];
    __nv_bfloat16 h0 = __float2bfloat16(x.x);
    __nv_bfloat16 h1 = __float2bfloat16(x.y);
    __nv_bfloat16 h2 = __float2bfloat16(x.z);
    __nv_bfloat16 h3 = __float2bfloat16(x.w);
    __nv_bfloat16 l0 = __float2bfloat16(x.x - __bfloat162float(h0));
    __nv_bfloat16 l1 = __float2bfloat16(x.y - __bfloat162float(h1));
    __nv_bfloat16 l2 = __float2bfloat16(x.z - __bfloat162float(h2));
    __nv_bfloat16 l3 = __float2bfloat16(x.w - __bfloat162float(h3));
    ((__nv_bfloat162*)H)[2*i]   = __nv_bfloat162(h0, h1);
    ((__nv_bfloat162*)H)[2*i+1] = __nv_bfloat162(h2, h3);
    ((__nv_bfloat162*)L)[2*i]   = __nv_bfloat162(l0, l1);
    ((__nv_bfloat162*)L)[2*i+1] = __nv_bfloat162(l2, l3);
    float4 r = make_float4(rna_tf32(x.x), rna_tf32(x.y),
                           rna_tf32(x.z), rna_tf32(x.w));
    ((float4*)R)[i] = r;
}

// ---------------------------------------------------------------------------
// W [K][N] fp32 -> transposed + bf16 split: TH/TL [N][K].  z picks matrix+slot.
// ---------------------------------------------------------------------------
__global__ __launch_bounds__(256) void wsplit3_kernel(
    const float* __restrict__ W0, const float* __restrict__ W1,
    const float* __restrict__ W2,
    __nv_bfloat16* __restrict__ TH, __nv_bfloat16* __restrict__ TL)
{
    __shared__ float t[32][33];
    const float* W = (blockIdx.z == 0) ? W0 : (blockIdx.z == 1) ? W1 : W2;
    __nv_bfloat16* th = TH + (long)blockIdx.z * DD * DD;
    __nv_bfloat16* tl = TL + (long)blockIdx.z * DD * DD;
    const int n0 = blockIdx.x * 32, k0 = blockIdx.y * 32;
    const int tx = threadIdx.x & 31, ty = threadIdx.x >> 5;
    #pragma unroll
    for (int i = 0; i < 32; i += 8)
        t[ty + i][tx] = W[(long)(k0 + ty + i) * DD + n0 + tx];
    __syncthreads();
    #pragma unroll
    for (int i = 0; i < 32; i += 8) {
        float x = t[tx][ty + i];
        long o = (long)(n0 + ty + i) * DD + k0 + tx;
        __nv_bfloat16 h = __float2bfloat16(x);
        th[o] = h;
        tl[o] = __float2bfloat16(x - __bfloat162float(h));
    }
}

// ---------------------------------------------------------------------------
// W [K][N] fp32 -> transposed + tf32-rounded fp32: T [N][K].  z picks matrix.
// ---------------------------------------------------------------------------
__global__ __launch_bounds__(256) void wT32_kernel(
    const float* __restrict__ W0, const float* __restrict__ W1,
    float* __restrict__ T)
{
    __shared__ float t[32][33];
    const float* W = blockIdx.z ? W1 : W0;
    float* out = T + (long)blockIdx.z * DD * DD;
    const int n0 = blockIdx.x * 32, k0 = blockIdx.y * 32;
    const int tx = threadIdx.x & 31, ty = threadIdx.x >> 5;
    #pragma unroll
    for (int i = 0; i < 32; i += 8)
        t[ty + i][tx] = W[(long)(k0 + ty + i) * DD + n0 + tx];
    __syncthreads();
    #pragma unroll
    for (int i = 0; i < 32; i += 8)
        out[(long)(n0 + ty + i) * DD + k0 + tx] = rna_tf32(t[tx][ty + i]);
}

// ---------------------------------------------------------------------------
// bf16x3 HMMA GEMM, packed-N weights (verified config: 3-stage, 2 CTAs/SM).
// ---------------------------------------------------------------------------
#define GKB      64
#define GNIT     96
#define GPAD     72
#define G_OPB    (128 * GPAD * 2)
#define G_STAGEB (2 * G_OPB)
#define GSMEM_TOTAL (3 * G_STAGEB)        // 110592 B

__device__ __forceinline__ void g_load_stage(
    uint32_t sbase, int stage, int tid,
    const __nv_bfloat16* __restrict__ Asrc, const __nv_bfloat16* __restrict__ Bsrc,
    long row0, long bcol0, int kc)
{
    const uint32_t abase = sbase + stage * G_STAGEB;
    const uint32_t bbase = abase + G_OPB;
    const __nv_bfloat16* Ap = Asrc + row0 * DD + kc;
    const __nv_bfloat16* Bp = Bsrc + bcol0 * DD + kc;
    #pragma unroll
    for (int i = 0; i < 4; i++) {
        int idx = i * 256 + tid;
        int r  = idx >> 3;
        int ch = idx & 7;
        uint32_t so = (uint32_t)(r * (GPAD * 2) + ch * 16);
        CP16(abase + so, Ap + (long)r * DD + ch * 8);
        CP16(bbase + so, Bp + (long)r * DD + ch * 8);
    }
}

__global__ __launch_bounds__(256, 2) void gemm_bf16x3_kernel(
    const __nv_bfloat16* __restrict__ Ahi, const __nv_bfloat16* __restrict__ Alo,
    const __nv_bfloat16* __restrict__ Bhi, const __nv_bfloat16* __restrict__ Blo,
    const float* __restrict__ bias, float* __restrict__ Cbase)
{
    extern __shared__ char gsm[];
    const uint32_t sb = smem_u32(gsm);
    const int tid  = threadIdx.x;
    const int wid  = tid >> 5;
    const int lane = tid & 31;
    const long bcol0 = (long)blockIdx.x * 128;
    const long row0  = (long)blockIdx.y * 128;
    const int  which = (int)(bcol0 >> 11);           // 0..1 (Q,K)
    const long cc0   = bcol0 & 2047;
    float* C = Cbase + (long)which * MD;

    const int warp_m = (wid >> 1) * 32;
    const int warp_n = (wid & 1) * 64;
    const int lr = lane & 15;
    const int hl = lane >> 4;

    float acc[2][8][4];
    #pragma unroll
    for (int mt = 0; mt < 2; mt++)
        #pragma unroll
        for (int nt = 0; nt < 8; nt++)
            #pragma unroll
            for (int e = 0; e < 4; e++)
                acc[mt][nt][e] = 0.0f;

    g_load_stage(sb, 0, tid, Ahi, Bhi, row0, bcol0, 0);
    CP_COMMIT();
    g_load_stage(sb, 1, tid, Ahi, Bhi, row0, bcol0, GKB);
    CP_COMMIT();

    int s = 0, ps = 2;
    #pragma unroll 1
    for (int it = 0; it < GNIT; it++) {
        CP_WAIT1();
        __syncthreads();

        const int nit = it + 2;
        if (nit < GNIT) {
            const int pass = nit >> 5;
            const int kc = (nit & 31) * GKB;
            const __nv_bfloat16* As = (pass == 2) ? Alo : Ahi;
            const __nv_bfloat16* Bs = (pass == 1) ? Blo : Bhi;
            g_load_stage(sb, ps, tid, As, Bs, row0, bcol0, kc);
        }
        CP_COMMIT();

        const uint32_t sA = sb + s * G_STAGEB;
        const uint32_t sB = sA + G_OPB;
        #pragma unroll
        for (int ks = 0; ks < 4; ks++) {
            const int k0 = ks * 16;
            uint32_t aF[2][4], bF[8][2];
            #pragma unroll
            for (int mt = 0; mt < 2; mt++) {
                uint32_t addr = sA + (uint32_t)((warp_m + mt * 16 + lr) * (GPAD * 2)
                                              + (k0 + 8 * hl) * 2);
                LDSM_X4(aF[mt][0], aF[mt][1], aF[mt][2], aF[mt][3], addr);
            }
            #pragma unroll
            for (int nt2 = 0; nt2 < 4; nt2++) {
                uint32_t r0, r1, r2, r3;
                uint32_t addr = sB + (uint32_t)((warp_n + nt2 * 16 + lr) * (GPAD * 2)
                                              + (k0 + 8 * hl) * 2);
                LDSM_X4(r0, r1, r2, r3, addr);
                bF[2 * nt2][0]     = r0;
                bF[2 * nt2 + 1][0] = r1;
                bF[2 * nt2][1]     = r2;
                bF[2 * nt2 + 1][1] = r3;
            }
            #pragma unroll
            for (int mt = 0; mt < 2; mt++)
                #pragma unroll
                for (int nt = 0; nt < 8; nt++)
                    MMA16816(acc[mt][nt], aF[mt], bF[nt]);
        }
        s = (s == 2) ? 0 : s + 1;
        ps = (ps == 2) ? 0 : ps + 1;
    }

    const int erow = lane >> 2;
    const int ecol = (lane & 3) * 2;
    #pragma unroll
    for (int mt = 0; mt < 2; mt++) {
        #pragma unroll
        for (int nt = 0; nt < 8; nt++) {
            const long r  = row0 + warp_m + mt * 16 + erow;
            const long cc = cc0 + warp_n + nt * 8 + ecol;
            float b0 = bias ? bias[cc] : 0.0f;
            float b1 = bias ? bias[cc + 1] : 0.0f;
            float2 v0 = make_float2(acc[mt][nt][0] + b0, acc[mt][nt][1] + b1);
            float2 v1 = make_float2(acc[mt][nt][2] + b0, acc[mt][nt][3] + b1);
            *(float2*)(C + r * DD + cc)       = v0;
            *(float2*)(C + (r + 8) * DD + cc) = v1;
        }
    }
}

// ---------------------------------------------------------------------------
// Single-pass TF32 GEMM with ldmatrix fragments (verified round 10).
// ---------------------------------------------------------------------------
#define TKB   32
#define TNIT  64
#define TPAD  36
#define T_OPB (128 * TPAD * 4)
#define T_STAGEB (2 * T_OPB)
#define TSMEM_TOTAL (3 * T_STAGEB)        // 110592 B

__device__ __forceinline__ void t_load_stage(
    uint32_t sbase, int stage, int tid,
    const float* __restrict__ Asrc, const float* __restrict__ Bsrc,
    long row0, long col0, int kc)
{
    const uint32_t abase = sbase + stage * T_STAGEB;
    const uint32_t bbase = abase + T_OPB;
    const float* Ap = Asrc + row0 * DD + kc;
    const float* Bp = Bsrc + col0 * DD + kc;
    #pragma unroll
    for (int i = 0; i < 4; i++) {
        int idx = i * 256 + tid;
        int r  = idx >> 3;
        int ch = idx & 7;
        uint32_t so = (uint32_t)(r * (TPAD * 4) + ch * 16);
        CP16(abase + so, Ap + (long)r * DD + ch * 4);
        CP16(bbase + so, Bp + (long)r * DD + ch * 4);
    }
}

__global__ __launch_bounds__(256, 2) void gemm_tf32_kernel(
    const float* __restrict__ A, const float* __restrict__ Bt,
    const float* __restrict__ bias, float* __restrict__ C)
{
    extern __shared__ char tsm[];
    const uint32_t sb = smem_u32(tsm);
    const int tid  = threadIdx.x;
    const int wid  = tid >> 5;
    const int lane = tid & 31;
    const long col0 = (long)blockIdx.x * 128;
    const long row0 = (long)blockIdx.y * 128;

    const int warp_m = (wid >> 1) * 32;
    const int warp_n = (wid & 1) * 64;

    const int a_row = lane & 15;
    const int a_kof = (lane >> 4) * 4;
    const int b_row = (lane & 7) + ((lane >> 4) << 3);
    const int b_kof = ((lane >> 3) & 1) * 4;

    float acc[2][8][4];
    #pragma unroll
    for (int mt = 0; mt < 2; mt++)
        #pragma unroll
        for (int nt = 0; nt < 8; nt++)
            #pragma unroll
            for (int e = 0; e < 4; e++)
                acc[mt][nt][e] = 0.0f;

    t_load_stage(sb, 0, tid, A, Bt, row0, col0, 0);
    CP_COMMIT();
    t_load_stage(sb, 1, tid, A, Bt, row0, col0, TKB);
    CP_COMMIT();

    int s = 0, ps = 2;
    #pragma unroll 1
    for (int it = 0; it < TNIT; it++) {
        CP_WAIT1();
        __syncthreads();

        const int nit = it + 2;
        if (nit < TNIT)
            t_load_stage(sb, ps, tid, A, Bt, row0, col0, nit * TKB);
        CP_COMMIT();

        const uint32_t sA = sb + s * T_STAGEB;
        const uint32_t sB = sA + T_OPB;
        #pragma unroll
        for (int ks = 0; ks < 4; ks++) {
            const int k0 = ks * 8;
            uint32_t aF[2][4], bF[8][2];
            #pragma unroll
            for (int mt = 0; mt < 2; mt++) {
                uint32_t addr = sA + (uint32_t)((warp_m + mt * 16 + a_row) * (TPAD * 4)
                                              + (k0 + a_kof) * 4);
                LDSM_X4(aF[mt][0], aF[mt][1], aF[mt][2], aF[mt][3], addr);
            }
            #pragma unroll
            for (int nt2 = 0; nt2 < 4; nt2++) {
                uint32_t r0, r1, r2, r3;
                uint32_t addr = sB + (uint32_t)((warp_n + nt2 * 16 + b_row) * (TPAD * 4)
                                              + (k0 + b_kof) * 4);
                LDSM_X4(r0, r1, r2, r3, addr);
                bF[2 * nt2][0]     = r0;
                bF[2 * nt2][1]     = r1;
                bF[2 * nt2 + 1][0] = r2;
                bF[2 * nt2 + 1][1] = r3;
            }
            #pragma unroll
            for (int mt = 0; mt < 2; mt++)
                #pragma unroll
                for (int nt = 0; nt < 8; nt++)
                    MMA_TF32(acc[mt][nt], aF[mt], bF[nt]);
        }
        s = (s == 2) ? 0 : s + 1;
        ps = (ps == 2) ? 0 : ps + 1;
    }

    const int erow = lane >> 2;
    const int ecol = (lane & 3) * 2;
    #pragma unroll
    for (int mt = 0; mt < 2; mt++) {
        #pragma unroll
        for (int nt = 0; nt < 8; nt++) {
            const long r  = row0 + warp_m + mt * 16 + erow;
            const long cc = col0 + warp_n + nt * 8 + ecol;
            float b0 = bias ? bias[cc] : 0.0f;
            float b1 = bias ? bias[cc + 1] : 0.0f;
            float2 v0 = make_float2(acc[mt][nt][0] + b0, acc[mt][nt][1] + b1);
            float2 v1 = make_float2(acc[mt][nt][2] + b0, acc[mt][nt][3] + b1);
            *(float2*)(C + r * DD + cc)       = v0;
            *(float2*)(C + (r + 8) * DD + cc) = v1;
        }
    }
}

// ---------------------------------------------------------------------------
// Local-window attention — round-10 version with QKPAD 68->64 (the inner-loop
// K read is 64 contiguous floats per warp, conflict-free at ANY stride, and
// the Q read is a 2-address broadcast, so the pad bought nothing) and
// __launch_bounds__(256,2): smem drops to 114688 B -> 2 CTAs/SM, the
// co-resident CTA hides the per-chunk K/V gmem latency + barrier stalls.
// ---------------------------------------------------------------------------
#define BQ   64
#define BKC  64
#define QKPAD 64
#define ATT_SMEM_BYTES ((128*QKPAD*2 + 64*128 + 64*64) * 4)   // 114688

__global__ __launch_bounds__(256, 2) void attn_local_kernel(
    const float* __restrict__ Q, const float* __restrict__ K,
    const float* __restrict__ V, const int* __restrict__ amask,
    float* __restrict__ O)
{
    const int q0 = blockIdx.x * BQ;
    const int h  = blockIdx.y;
    const int b  = blockIdx.z;

    extern __shared__ float sm[];
    float* Qs  = sm;                       // [128][64] d-major, qi contiguous
    float* Ks  = Qs + 128 * QKPAD;         // [128][64]
    float* Vs  = Ks + 128 * QKPAD;         // [64][128]
    float* PsT = Vs + 64 * 128;            // [64][64] rotated

    const int tid = threadIdx.x;
    const int r   = tid >> 4;              // q rows r*4..r*4+3
    const int c   = tid & 15;

    const float* qbase = Q + ((long)(b * SS + q0)) * DD + h * HDIM;
    #pragma unroll
    for (int e = tid; e < BQ * (HDIM / 4); e += 256) {
        int qi = e >> 5, d4 = e & 31;
        float4 f = *(const float4*)(qbase + (long)qi * DD + d4 * 4);
        Qs[(d4 * 4 + 0) * QKPAD + qi] = f.x;
        Qs[(d4 * 4 + 1) * QKPAD + qi] = f.y;
        Qs[(d4 * 4 + 2) * QKPAD + qi] = f.z;
        Qs[(d4 * 4 + 3) * QKPAD + qi] = f.w;
    }

    float m[4], l[4], o[4][8];
    #pragma unroll
    for (int i = 0; i < 4; i++) {
        m[i] = -FLT_MAX; l[i] = 0.0f;
        #pragma unroll
        for (int dd = 0; dd < 8; dd++) o[i][dd] = 0.0f;
    }

    for (int t = 0; t < 5; t++) {
        const int kb = q0 - WINDOW + t * BKC;
        if (kb < 0) continue;

        __syncthreads();

        const float* kbase = K + ((long)(b * SS + kb)) * DD + h * HDIM;
        const float* vbase = V + ((long)(b * SS + kb)) * DD + h * HDIM;
        #pragma unroll
        for (int e = tid; e < BKC * (HDIM / 4); e += 256) {
            int kj = e >> 5, d4 = e & 31;
            float4 kf = *(const float4*)(kbase + (long)kj * DD + d4 * 4);
            float4 vf = *(const float4*)(vbase + (long)kj * DD + d4 * 4);
            Ks[(d4 * 4 + 0) * QKPAD + kj] = kf.x;
            Ks[(d4 * 4 + 1) * QKPAD + kj] = kf.y;
            Ks[(d4 * 4 + 2) * QKPAD + kj] = kf.z;
            Ks[(d4 * 4 + 3) * QKPAD + kj] = kf.w;
            *(float4*)&Vs[kj * 128 + d4 * 4] = vf;
        }
        const int4 mk4 = *(const int4*)(amask + b * SS + kb + c * 4);
        __syncthreads();

        float s[4][4];
        #pragma unroll
        for (int i = 0; i < 4; i++)
            #pragma unroll
            for (int j = 0; j < 4; j++) s[i][j] = 0.0f;

        #pragma unroll 4
        for (int d = 0; d < HDIM; d++) {
            float4 q4 = *(const float4*)&Qs[d * QKPAD + r * 4];
            float4 k4 = *(const float4*)&Ks[d * QKPAD + c * 4];
            const float qv[4] = {q4.x, q4.y, q4.z, q4.w};
            const float kv[4] = {k4.x, k4.y, k4.z, k4.w};
            #pragma unroll
            for (int i = 0; i < 4; i++)
                #pragma unroll
                for (int j = 0; j < 4; j++)
                    s[i][j] = fmaf(qv[i], kv[j], s[i][j]);
        }

        const int mok[4] = {mk4.x, mk4.y, mk4.z, mk4.w};
        float scl[4];
        #pragma unroll
        for (int i = 0; i < 4; i++) {
            const int qi = q0 + r * 4 + i;
            #pragma unroll
            for (int j = 0; j < 4; j++) {
                const int kj = kb + c * 4 + j;
                bool ok = (kj <= qi) && (kj > qi - WINDOW) && (mok[j] > 0);
                if (!ok) s[i][j] = -FLT_MAX;
            }
            float mx = fmaxf(fmaxf(s[i][0], s[i][1]), fmaxf(s[i][2], s[i][3]));
            #pragma unroll
            for (int w = 1; w <= 8; w <<= 1)
                mx = fmaxf(mx, __shfl_xor_sync(0xffffffffu, mx, w));

            float mnew = fmaxf(m[i], mx);
            scl[i] = __expf(m[i] - mnew);
            m[i] = mnew;

            float sum = 0.0f;
            #pragma unroll
            for (int j = 0; j < 4; j++) {
                float p = (s[i][j] > -1e37f) ? __expf(s[i][j] - mnew) : 0.0f;
                s[i][j] = p;
                sum += p;
            }
            #pragma unroll
            for (int w = 1; w <= 8; w <<= 1)
                sum += __shfl_xor_sync(0xffffffffu, sum, w);

            l[i] = l[i] * scl[i] + sum;
            #pragma unroll
            for (int dd = 0; dd < 8; dd++) o[i][dd] *= scl[i];
        }

        #pragma unroll
        for (int j = 0; j < 4; j++) {
            int row  = c * 4 + j;
            int wcol = (4 * r + 4 * c) & 63;
            *(float4*)&PsT[row * 64 + wcol] =
                make_float4(s[0][j], s[1][j], s[2][j], s[3][j]);
        }
        __syncthreads();

        #pragma unroll 8
        for (int j = 0; j < BKC; j++) {
            int wcol = (4 * r + 4 * (j >> 2)) & 63;
            float4 p4 = *(const float4*)&PsT[j * 64 + wcol];
            float4 va = *(const float4*)&Vs[j * 128 + c * 8];
            float4 vb = *(const float4*)&Vs[j * 128 + c * 8 + 4];
            const float pv[4] = {p4.x, p4.y, p4.z, p4.w};
            const float vv[8] = {va.x, va.y, va.z, va.w, vb.x, vb.y, vb.z, vb.w};
            #pragma unroll
            for (int i = 0; i < 4; i++)
                #pragma unroll
                for (int dd = 0; dd < 8; dd++)
                    o[i][dd] = fmaf(pv[i], vv[dd], o[i][dd]);
        }
    }

    #pragma unroll
    for (int i = 0; i < 4; i++) {
        const int row = q0 + r * 4 + i;
        const float inv = 1.0f / l[i];
        const long base = ((long)(b * SS + row)) * DD + h * HDIM + c * 8;
        float out[8];
        #pragma unroll
        for (int dd = 0; dd < 8; dd++) out[dd] = rna_tf32(o[i][dd] * inv);
        *(float4*)(O + base)     = make_float4(out[0], out[1], out[2], out[3]);
        *(float4*)(O + base + 4) = make_float4(out[4], out[5], out[6], out[7]);
    }
}

// ---------------------------------------------------------------------------
// Launch
// ---------------------------------------------------------------------------
extern "C" void kernel_launch(void* const* d_in, const int* in_sizes, int n_in,
                              void* d_out, int out_size)
{
    const float* hs    = (const float*)d_in[0];
    const int*   amask = (const int*)  d_in[1];
    const float* Wq    = (const float*)d_in[2];
    const float* Wk    = (const float*)d_in[3];
    const float* Wv    = (const float*)d_in[4];
    const float* Wo    = (const float*)d_in[5];
    const float* bo    = (const float*)d_in[6];
    float*       out   = (float*)d_out;

    float *qkv, *ao, *wT;
    __nv_bfloat16 *ahi, *alo, *whi, *wlo;
    cudaGetSymbolAddress((void**)&qkv, g_qkv);
    cudaGetSymbolAddress((void**)&ao,  g_ao);
    cudaGetSymbolAddress((void**)&ahi, g_ahi);
    cudaGetSymbolAddress((void**)&alo, g_alo);
    cudaGetSymbolAddress((void**)&whi, g_whi);
    cudaGetSymbolAddress((void**)&wlo, g_wlo);
    cudaGetSymbolAddress((void**)&wT,  g_wT);

    cudaFuncSetAttribute(gemm_bf16x3_kernel,
                         cudaFuncAttributeMaxDynamicSharedMemorySize, GSMEM_TOTAL);
    cudaFuncSetAttribute(gemm_tf32_kernel,
                         cudaFuncAttributeMaxDynamicSharedMemorySize, TSMEM_TOTAL);
    cudaFuncSetAttribute(attn_local_kernel,
                         cudaFuncAttributeMaxDynamicSharedMemorySize, ATT_SMEM_BYTES);

    const int n4 = MROWS * DD / 4;

    // (1) hs -> bf16 hi/lo + tf32-rounded fp32 (in g_ao)
    split3_kernel<<<(n4 + 255) / 256, 256>>>(hs, ahi, alo, ao, n4);

    // (2) Wq/Wk -> bf16 transposed split
    dim3 wgrid2(DD / 32, DD / 32, 2);
    wsplit3_kernel<<<wgrid2, 256>>>(Wq, Wk, Wk, whi, wlo);

    // (3) Wv/Wo -> tf32-rounded fp32 transpose
    wT32_kernel<<<wgrid2, 256>>>(Wv, Wo, wT);

    // (4) V GEMM (single-pass tf32)
    dim3 tgrid(DD / 128, MROWS / 128);
    gemm_tf32_kernel<<<tgrid, 256, TSMEM_TOTAL>>>(ao, wT, nullptr, qkv + 2 * MD);

    // (5) fused QK GEMM (bf16x3)
    dim3 qkgrid(2 * DD / 128, MROWS / 128);
    gemm_bf16x3_kernel<<<qkgrid, 256, GSMEM_TOTAL>>>(ahi, alo, whi, wlo, nullptr, qkv);

    // (6) attention: overwrites g_ao with tf32-rounded output
    dim3 attn_grid(SS / BQ, HH, BB);
    attn_local_kernel<<<attn_grid, 256, ATT_SMEM_BYTES>>>(
        qkv, qkv + MD, qkv + 2 * MD, amask, ao);

    // (7) output projection (single-pass tf32)
    gemm_tf32_kernel<<<tgrid, 256, TSMEM_TOTAL>>>(ao, wT + (long)DD * DD, bo, out);
}

// round 15
// speedup vs baseline: 1.1834x; 1.1510x over previous
#include <cuda_runtime.h>
#include <cuda_bf16.h>
#include <float.h>
#include <stdint.h>

// Problem constants
#define BB     2
#define SS     2048
#define DD     2048
#define HH     16
#define HDIM   128
#define WINDOW 256
#define MROWS  (BB * SS)   // 4096
#define MD     ((long)MROWS * DD)

// ---------------------------------------------------------------------------
// Scratch (device globals — no allocation allowed)
// ---------------------------------------------------------------------------
__device__ float g_qkv[3 * MROWS * DD];       // q | k | v
__device__ float g_ao [MROWS * DD];           // rna(hs) first, then attn output
__device__ __nv_bfloat16 g_ahi[MROWS * DD];
__device__ __nv_bfloat16 g_alo[MROWS * DD];
__device__ __nv_bfloat16 g_whi[2 * DD * DD];  // Wq | Wk  (bf16 hi)
__device__ __nv_bfloat16 g_wlo[2 * DD * DD];  // Wq | Wk  (bf16 lo)
__device__ float g_wT[2 * DD * DD];           // WvT | WoT (tf32-rounded fp32)

// ---------------------------------------------------------------------------
// PTX helpers (family-wide only: harness emits compute_103 PTX -> no tcgen05)
// ---------------------------------------------------------------------------
__device__ __forceinline__ uint32_t smem_u32(const void* p) {
    uint32_t a;
    asm("{ .reg .u64 t; cvta.to.shared.u64 t, %1; cvt.u32.u64 %0, t; }"
        : "=r"(a) : "l"(p));
    return a;
}

__device__ __forceinline__ float rna_tf32(float x) {
    float y;
    asm("cvt.rna.tf32.f32 %0, %1;" : "=f"(y) : "f"(x));
    return y;
}

#define CP16(dst, src) \
    asm volatile("cp.async.cg.shared.global [%0], [%1], 16;" :: "r"(dst), "l"(src))
#define CP_COMMIT() asm volatile("cp.async.commit_group;" ::: "memory")
#define CP_WAIT1()  asm volatile("cp.async.wait_group 1;" ::: "memory")

#define LDSM_X4(r0, r1, r2, r3, addr) \
    asm volatile("ldmatrix.sync.aligned.m8n8.x4.shared.b16 {%0,%1,%2,%3}, [%4];" \
        : "=r"(r0), "=r"(r1), "=r"(r2), "=r"(r3) : "r"(addr))

#define MMA16816(d, a, b) \
    asm volatile("mma.sync.aligned.m16n8k16.row.col.f32.bf16.bf16.f32 " \
        "{%0,%1,%2,%3}, {%4,%5,%6,%7}, {%8,%9}, {%0,%1,%2,%3};" \
        : "+f"((d)[0]), "+f"((d)[1]), "+f"((d)[2]), "+f"((d)[3]) \
        : "r"((a)[0]), "r"((a)[1]), "r"((a)[2]), "r"((a)[3]), \
          "r"((b)[0]), "r"((b)[1]))

#define MMA_TF32(d, a, b) \
    asm volatile("mma.sync.aligned.m16n8k8.row.col.f32.tf32.tf32.f32 " \
        "{%0,%1,%2,%3}, {%4,%5,%6,%7}, {%8,%9}, {%0,%1,%2,%3};" \
        : "+f"((d)[0]), "+f"((d)[1]), "+f"((d)[2]), "+f"((d)[3]) \
        : "r"((a)[0]), "r"((a)[1]), "r"((a)[2]), "r"((a)[3]), \
          "r"((b)[0]), "r"((b)[1]))

// ---------------------------------------------------------------------------
// Split fp32 -> bf16 hi + lo AND tf32-rounded fp32 copy (for the tf32 V gemm)
// ---------------------------------------------------------------------------
__global__ __launch_bounds__(256) void split3_kernel(
    const float* __restrict__ X, __nv_bfloat16* __restrict__ H,
    __nv_bfloat16* __restrict__ L, float* __restrict__ R, int n4)
{
    int i = blockIdx.x * blockDim.x + threadIdx.x;
    if (i >= n4) return;
    float4 x = ((const float4*)X)[i];
    __nv_bfloat16 h0 = __float2bfloat16(x.x);
    __nv_bfloat16 h1 = __float2bfloat16(x.y);
    __nv_bfloat16 h2 = __float2bfloat16(x.z);
    __nv_bfloat16 h3 = __float2bfloat16(x.w);
    __nv_bfloat16 l0 = __float2bfloat16(x.x - __bfloat162float(h0));
    __nv_bfloat16 l1 = __float2bfloat16(x.y - __bfloat162float(h1));
    __nv_bfloat16 l2 = __float2bfloat16(x.z - __bfloat162float(h2));
    __nv_bfloat16 l3 = __float2bfloat16(x.w - __bfloat162float(h3));
    ((__nv_bfloat162*)H)[2*i]   = __nv_bfloat162(h0, h1);
    ((__nv_bfloat162*)H)[2*i+1] = __nv_bfloat162(h2, h3);
    ((__nv_bfloat162*)L)[2*i]   = __nv_bfloat162(l0, l1);
    ((__nv_bfloat162*)L)[2*i+1] = __nv_bfloat162(l2, l3);
    float4 r = make_float4(rna_tf32(x.x), rna_tf32(x.y),
                           rna_tf32(x.z), rna_tf32(x.w));
    ((float4*)R)[i] = r;
}

// ---------------------------------------------------------------------------
// Weight prep, one launch: z 0..1 -> bf16 transposed split of Wq/Wk;
// z 2..3 -> tf32-rounded transpose of Wv/Wo.
// ---------------------------------------------------------------------------
__global__ __launch_bounds__(256) void wprep_kernel(
    const float* __restrict__ Wq, const float* __restrict__ Wk,
    const float* __restrict__ Wv, const float* __restrict__ Wo,
    __nv_bfloat16* __restrict__ TH, __nv_bfloat16* __restrict__ TL,
    float* __restrict__ T32)
{
    __shared__ float t[32][33];
    const int z = blockIdx.z;
    const float* W = (z == 0) ? Wq : (z == 1) ? Wk : (z == 2) ? Wv : Wo;
    const int n0 = blockIdx.x * 32, k0 = blockIdx.y * 32;
    const int tx = threadIdx.x & 31, ty = threadIdx.x >> 5;
    #pragma unroll
    for (int i = 0; i < 32; i += 8)
        t[ty + i][tx] = W[(long)(k0 + ty + i) * DD + n0 + tx];
    __syncthreads();
    if (z < 2) {
        __nv_bfloat16* th = TH + (long)z * DD * DD;
        __nv_bfloat16* tl = TL + (long)z * DD * DD;
        #pragma unroll
        for (int i = 0; i < 32; i += 8) {
            float x = t[tx][ty + i];
            long o = (long)(n0 + ty + i) * DD + k0 + tx;
            __nv_bfloat16 h = __float2bfloat16(x);
            th[o] = h;
            tl[o] = __float2bfloat16(x - __bfloat162float(h));
        }
    } else {
        float* out = T32 + (long)(z - 2) * DD * DD;
        #pragma unroll
        for (int i = 0; i < 32; i += 8)
            out[(long)(n0 + ty + i) * DD + k0 + tx] = rna_tf32(t[tx][ty + i]);
    }
}

// ---------------------------------------------------------------------------
// bf16x3 HMMA GEMM, packed-N weights (verified: 3-stage, 2 CTAs/SM).
// ---------------------------------------------------------------------------
#define GKB      64
#define GNIT     96
#define GPAD     72
#define G_OPB    (128 * GPAD * 2)
#define G_STAGEB (2 * G_OPB)
#define GSMEM_TOTAL (3 * G_STAGEB)        // 110592 B

__device__ __forceinline__ void g_load_stage(
    uint32_t sbase, int stage, int tid,
    const __nv_bfloat16* __restrict__ Asrc, const __nv_bfloat16* __restrict__ Bsrc,
    long row0, long bcol0, int kc)
{
    const uint32_t abase = sbase + stage * G_STAGEB;
    const uint32_t bbase = abase + G_OPB;
    const __nv_bfloat16* Ap = Asrc + row0 * DD + kc;
    const __nv_bfloat16* Bp = Bsrc + bcol0 * DD + kc;
    #pragma unroll
    for (int i = 0; i < 4; i++) {
        int idx = i * 256 + tid;
        int r  = idx >> 3;
        int ch = idx & 7;
        uint32_t so = (uint32_t)(r * (GPAD * 2) + ch * 16);
        CP16(abase + so, Ap + (long)r * DD + ch * 8);
        CP16(bbase + so, Bp + (long)r * DD + ch * 8);
    }
}

__global__ __launch_bounds__(256, 2) void gemm_bf16x3_kernel(
    const __nv_bfloat16* __restrict__ Ahi, const __nv_bfloat16* __restrict__ Alo,
    const __nv_bfloat16* __restrict__ Bhi, const __nv_bfloat16* __restrict__ Blo,
    const float* __restrict__ bias, float* __restrict__ Cbase)
{
    extern __shared__ char gsm[];
    const uint32_t sb = smem_u32(gsm);
    const int tid  = threadIdx.x;
    const int wid  = tid >> 5;
    const int lane = tid & 31;
    const long bcol0 = (long)blockIdx.x * 128;
    const long row0  = (long)blockIdx.y * 128;
    const int  which = (int)(bcol0 >> 11);           // 0..1 (Q,K)
    const long cc0   = bcol0 & 2047;
    float* C = Cbase + (long)which * MD;

    const int warp_m = (wid >> 1) * 32;
    const int warp_n = (wid & 1) * 64;
    const int lr = lane & 15;
    const int hl = lane >> 4;

    float acc[2][8][4];
    #pragma unroll
    for (int mt = 0; mt < 2; mt++)
        #pragma unroll
        for (int nt = 0; nt < 8; nt++)
            #pragma unroll
            for (int e = 0; e < 4; e++)
                acc[mt][nt][e] = 0.0f;

    g_load_stage(sb, 0, tid, Ahi, Bhi, row0, bcol0, 0);
    CP_COMMIT();
    g_load_stage(sb, 1, tid, Ahi, Bhi, row0, bcol0, GKB);
    CP_COMMIT();

    int s = 0, ps = 2;
    #pragma unroll 1
    for (int it = 0; it < GNIT; it++) {
        CP_WAIT1();
        __syncthreads();

        const int nit = it + 2;
        if (nit < GNIT) {
            const int pass = nit >> 5;
            const int kc = (nit & 31) * GKB;
            const __nv_bfloat16* As = (pass == 2) ? Alo : Ahi;
            const __nv_bfloat16* Bs = (pass == 1) ? Blo : Bhi;
            g_load_stage(sb, ps, tid, As, Bs, row0, bcol0, kc);
        }
        CP_COMMIT();

        const uint32_t sA = sb + s * G_STAGEB;
        const uint32_t sB = sA + G_OPB;
        #pragma unroll
        for (int ks = 0; ks < 4; ks++) {
            const int k0 = ks * 16;
            uint32_t aF[2][4], bF[8][2];
            #pragma unroll
            for (int mt = 0; mt < 2; mt++) {
                uint32_t addr = sA + (uint32_t)((warp_m + mt * 16 + lr) * (GPAD * 2)
                                              + (k0 + 8 * hl) * 2);
                LDSM_X4(aF[mt][0], aF[mt][1], aF[mt][2], aF[mt][3], addr);
            }
            #pragma unroll
            for (int nt2 = 0; nt2 < 4; nt2++) {
                uint32_t r0, r1, r2, r3;
                uint32_t addr = sB + (uint32_t)((warp_n + nt2 * 16 + lr) * (GPAD * 2)
                                              + (k0 + 8 * hl) * 2);
                LDSM_X4(r0, r1, r2, r3, addr);
                bF[2 * nt2][0]     = r0;
                bF[2 * nt2 + 1][0] = r1;
                bF[2 * nt2][1]     = r2;
                bF[2 * nt2 + 1][1] = r3;
            }
            #pragma unroll
            for (int mt = 0; mt < 2; mt++)
                #pragma unroll
                for (int nt = 0; nt < 8; nt++)
                    MMA16816(acc[mt][nt], aF[mt], bF[nt]);
        }
        s = (s == 2) ? 0 : s + 1;
        ps = (ps == 2) ? 0 : ps + 1;
    }

    const int erow = lane >> 2;
    const int ecol = (lane & 3) * 2;
    #pragma unroll
    for (int mt = 0; mt < 2; mt++) {
        #pragma unroll
        for (int nt = 0; nt < 8; nt++) {
            const long r  = row0 + warp_m + mt * 16 + erow;
            const long cc = cc0 + warp_n + nt * 8 + ecol;
            float b0 = bias ? bias[cc] : 0.0f;
            float b1 = bias ? bias[cc + 1] : 0.0f;
            float2 v0 = make_float2(acc[mt][nt][0] + b0, acc[mt][nt][1] + b1);
            float2 v1 = make_float2(acc[mt][nt][2] + b0, acc[mt][nt][3] + b1);
            *(float2*)(C + r * DD + cc)       = v0;
            *(float2*)(C + (r + 8) * DD + cc) = v1;
        }
    }
}

// ---------------------------------------------------------------------------
// Single-pass TF32 GEMM with ldmatrix fragments (verified round 10).
// ---------------------------------------------------------------------------
#define TKB   32
#define TNIT  64
#define TPAD  36
#define T_OPB (128 * TPAD * 4)
#define T_STAGEB (2 * T_OPB)
#define TSMEM_TOTAL (3 * T_STAGEB)        // 110592 B

__device__ __forceinline__ void t_load_stage(
    uint32_t sbase, int stage, int tid,
    const float* __restrict__ Asrc, const float* __restrict__ Bsrc,
    long row0, long col0, int kc)
{
    const uint32_t abase = sbase + stage * T_STAGEB;
    const uint32_t bbase = abase + T_OPB;
    const float* Ap = Asrc + row0 * DD + kc;
    const float* Bp = Bsrc + col0 * DD + kc;
    #pragma unroll
    for (int i = 0; i < 4; i++) {
        int idx = i * 256 + tid;
        int r  = idx >> 3;
        int ch = idx & 7;
        uint32_t so = (uint32_t)(r * (TPAD * 4) + ch * 16);
        CP16(abase + so, Ap + (long)r * DD + ch * 4);
        CP16(bbase + so, Bp + (long)r * DD + ch * 4);
    }
}

__global__ __launch_bounds__(256, 2) void gemm_tf32_kernel(
    const float* __restrict__ A, const float* __restrict__ Bt,
    const float* __restrict__ bias, float* __restrict__ C)
{
    extern __shared__ char tsm[];
    const uint32_t sb = smem_u32(tsm);
    const int tid  = threadIdx.x;
    const int wid  = tid >> 5;
    const int lane = tid & 31;
    const long col0 = (long)blockIdx.x * 128;
    const long row0 = (long)blockIdx.y * 128;

    const int warp_m = (wid >> 1) * 32;
    const int warp_n = (wid & 1) * 64;

    const int a_row = lane & 15;
    const int a_kof = (lane >> 4) * 4;
    const int b_row = (lane & 7) + ((lane >> 4) << 3);
    const int b_kof = ((lane >> 3) & 1) * 4;

    float acc[2][8][4];
    #pragma unroll
    for (int mt = 0; mt < 2; mt++)
        #pragma unroll
        for (int nt = 0; nt < 8; nt++)
            #pragma unroll
            for (int e = 0; e < 4; e++)
                acc[mt][nt][e] = 0.0f;

    t_load_stage(sb, 0, tid, A, Bt, row0, col0, 0);
    CP_COMMIT();
    t_load_stage(sb, 1, tid, A, Bt, row0, col0, TKB);
    CP_COMMIT();

    int s = 0, ps = 2;
    #pragma unroll 1
    for (int it = 0; it < TNIT; it++) {
        CP_WAIT1();
        __syncthreads();

        const int nit = it + 2;
        if (nit < TNIT)
            t_load_stage(sb, ps, tid, A, Bt, row0, col0, nit * TKB);
        CP_COMMIT();

        const uint32_t sA = sb + s * T_STAGEB;
        const uint32_t sB = sA + T_OPB;
        #pragma unroll
        for (int ks = 0; ks < 4; ks++) {
            const int k0 = ks * 8;
            uint32_t aF[2][4], bF[8][2];
            #pragma unroll
            for (int mt = 0; mt < 2; mt++) {
                uint32_t addr = sA + (uint32_t)((warp_m + mt * 16 + a_row) * (TPAD * 4)
                                              + (k0 + a_kof) * 4);
                LDSM_X4(aF[mt][0], aF[mt][1], aF[mt][2], aF[mt][3], addr);
            }
            #pragma unroll
            for (int nt2 = 0; nt2 < 4; nt2++) {
                uint32_t r0, r1, r2, r3;
                uint32_t addr = sB + (uint32_t)((warp_n + nt2 * 16 + b_row) * (TPAD * 4)
                                              + (k0 + b_kof) * 4);
                LDSM_X4(r0, r1, r2, r3, addr);
                bF[2 * nt2][0]     = r0;
                bF[2 * nt2][1]     = r1;
                bF[2 * nt2 + 1][0] = r2;
                bF[2 * nt2 + 1][1] = r3;
            }
            #pragma unroll
            for (int mt = 0; mt < 2; mt++)
                #pragma unroll
                for (int nt = 0; nt < 8; nt++)
                    MMA_TF32(acc[mt][nt], aF[mt], bF[nt]);
        }
        s = (s == 2) ? 0 : s + 1;
        ps = (ps == 2) ? 0 : ps + 1;
    }

    const int erow = lane >> 2;
    const int ecol = (lane & 3) * 2;
    #pragma unroll
    for (int mt = 0; mt < 2; mt++) {
        #pragma unroll
        for (int nt = 0; nt < 8; nt++) {
            const long r  = row0 + warp_m + mt * 16 + erow;
            const long cc = col0 + warp_n + nt * 8 + ecol;
            float b0 = bias ? bias[cc] : 0.0f;
            float b1 = bias ? bias[cc + 1] : 0.0f;
            float2 v0 = make_float2(acc[mt][nt][0] + b0, acc[mt][nt][1] + b1);
            float2 v1 = make_float2(acc[mt][nt][2] + b0, acc[mt][nt][3] + b1);
            *(float2*)(C + r * DD + cc)       = v0;
            *(float2*)(C + (r + 8) * DD + cc) = v1;
        }
    }
}

// ---------------------------------------------------------------------------
// Local-window attention — S = Q@K^T on bf16x3 HMMA.  ROUND-15 FIX: bf16 row
// pitch was 72 (copied from the 64-elem GEMM rows) but attention rows are 128
// elems -> rows overlapped, total corruption.  Correct pitch: 136 bf16 =
// 272 B ≡ 16 mod 128 -> LDSM phases conflict-free.  smem 119808 B, 1 CTA/SM.
// ---------------------------------------------------------------------------
#define BQ   64
#define BKC  64
#define SQP  136                           // bf16 row pitch (272 B)
#define PP   68                            // PsT pitch in floats (272 B)
#define A_QH 0
#define A_QL (A_QH + 64 * SQP * 2)         // 17408
#define A_KH (A_QL + 64 * SQP * 2)         // 34816
#define A_KL (A_KH + 64 * SQP * 2)         // 52224
#define A_VS (A_KL + 64 * SQP * 2)         // 69632
#define A_PS (A_VS + 64 * 128 * 4)         // 102400
#define ATT_SMEM_BYTES (A_PS + 64 * PP * 4)  // 119808

__global__ __launch_bounds__(256, 1) void attn_local_kernel(
    const float* __restrict__ Q, const float* __restrict__ K,
    const float* __restrict__ V, const int* __restrict__ amask,
    float* __restrict__ O)
{
    const int q0 = blockIdx.x * BQ;
    const int h  = blockIdx.y;
    const int b  = blockIdx.z;

    extern __shared__ char asmem[];
    const uint32_t sb = smem_u32(asmem);
    __nv_bfloat16* Qh = (__nv_bfloat16*)(asmem + A_QH);
    __nv_bfloat16* Ql = (__nv_bfloat16*)(asmem + A_QL);
    __nv_bfloat16* Kh = (__nv_bfloat16*)(asmem + A_KH);
    __nv_bfloat16* Kl = (__nv_bfloat16*)(asmem + A_KL);
    float* Vs  = (float*)(asmem + A_VS);
    float* PsT = (float*)(asmem + A_PS);

    const int tid  = threadIdx.x;
    const int wid  = tid >> 5;
    const int lane = tid & 31;
    const int r    = tid >> 4;             // softmax/PV mapping (q rows r*4+i)
    const int c    = tid & 15;             // key cols c*4+j
    const int wm   = (wid & 3) * 16;       // S warp tile: rows
    const int wn   = (wid >> 2) * 32;      // S warp tile: cols
    const int lr   = lane & 15;
    const int hl   = lane >> 4;

    // Q staging: fp32 -> bf16 hi/lo, row-major pitch 136
    const float* qbase = Q + ((long)(b * SS + q0)) * DD + h * HDIM;
    #pragma unroll
    for (int e = tid; e < BQ * (HDIM / 4); e += 256) {
        int qi = e >> 5, d4 = e & 31;
        float4 f = *(const float4*)(qbase + (long)qi * DD + d4 * 4);
        __nv_bfloat16 h0 = __float2bfloat16(f.x), h1 = __float2bfloat16(f.y);
        __nv_bfloat16 h2 = __float2bfloat16(f.z), h3 = __float2bfloat16(f.w);
        *(__nv_bfloat162*)&Qh[qi * SQP + d4 * 4]     = __nv_bfloat162(h0, h1);
        *(__nv_bfloat162*)&Qh[qi * SQP + d4 * 4 + 2] = __nv_bfloat162(h2, h3);
        __nv_bfloat16 l0 = __float2bfloat16(f.x - __bfloat162float(h0));
        __nv_bfloat16 l1 = __float2bfloat16(f.y - __bfloat162float(h1));
        __nv_bfloat16 l2 = __float2bfloat16(f.z - __bfloat162float(h2));
        __nv_bfloat16 l3 = __float2bfloat16(f.w - __bfloat162float(h3));
        *(__nv_bfloat162*)&Ql[qi * SQP + d4 * 4]     = __nv_bfloat162(l0, l1);
        *(__nv_bfloat162*)&Ql[qi * SQP + d4 * 4 + 2] = __nv_bfloat162(l2, l3);
    }

    float m[4], l[4], o[4][8];
    #pragma unroll
    for (int i = 0; i < 4; i++) {
        m[i] = -FLT_MAX; l[i] = 0.0f;
        #pragma unroll
        for (int dd = 0; dd < 8; dd++) o[i][dd] = 0.0f;
    }

    for (int t = 0; t < 5; t++) {
        const int kb = q0 - WINDOW + t * BKC;
        if (kb < 0) continue;

        __syncthreads();   // prev chunk done with Kh/Kl/Vs/PsT

        const float* kbase = K + ((long)(b * SS + kb)) * DD + h * HDIM;
        const float* vbase = V + ((long)(b * SS + kb)) * DD + h * HDIM;
        #pragma unroll
        for (int e = tid; e < BKC * (HDIM / 4); e += 256) {
            int kj = e >> 5, d4 = e & 31;
            float4 kf = *(const float4*)(kbase + (long)kj * DD + d4 * 4);
            float4 vf = *(const float4*)(vbase + (long)kj * DD + d4 * 4);
            __nv_bfloat16 h0 = __float2bfloat16(kf.x), h1 = __float2bfloat16(kf.y);
            __nv_bfloat16 h2 = __float2bfloat16(kf.z), h3 = __float2bfloat16(kf.w);
            *(__nv_bfloat162*)&Kh[kj * SQP + d4 * 4]     = __nv_bfloat162(h0, h1);
            *(__nv_bfloat162*)&Kh[kj * SQP + d4 * 4 + 2] = __nv_bfloat162(h2, h3);
            __nv_bfloat16 l0 = __float2bfloat16(kf.x - __bfloat162float(h0));
            __nv_bfloat16 l1 = __float2bfloat16(kf.y - __bfloat162float(h1));
            __nv_bfloat16 l2 = __float2bfloat16(kf.z - __bfloat162float(h2));
            __nv_bfloat16 l3 = __float2bfloat16(kf.w - __bfloat162float(h3));
            *(__nv_bfloat162*)&Kl[kj * SQP + d4 * 4]     = __nv_bfloat162(l0, l1);
            *(__nv_bfloat162*)&Kl[kj * SQP + d4 * 4 + 2] = __nv_bfloat162(l2, l3);
            *(float4*)&Vs[kj * 128 + d4 * 4] = vf;
        }
        const int4 mk4 = *(const int4*)(amask + b * SS + kb + c * 4);
        __syncthreads();   // staging visible

        // S = Qh*Kh + Qh*Kl + Ql*Kh on HMMA (warp tile 16x32)
        float acc4[4][4];
        #pragma unroll
        for (int nt = 0; nt < 4; nt++)
            #pragma unroll
            for (int e = 0; e < 4; e++) acc4[nt][e] = 0.0f;

        #pragma unroll
        for (int p = 0; p < 3; p++) {
            const uint32_t aB = sb + ((p == 2) ? A_QL : A_QH);
            const uint32_t bB = sb + ((p == 1) ? A_KL : A_KH);
            #pragma unroll
            for (int ks = 0; ks < 8; ks++) {
                const int k0 = ks * 16;
                uint32_t aF[4], bF[4][2];
                LDSM_X4(aF[0], aF[1], aF[2], aF[3],
                        aB + (uint32_t)((wm + lr) * (SQP * 2) + (k0 + 8 * hl) * 2));
                #pragma unroll
                for (int nt2 = 0; nt2 < 2; nt2++) {
                    uint32_t r0, r1, r2, r3;
                    LDSM_X4(r0, r1, r2, r3,
                            bB + (uint32_t)((wn + nt2 * 16 + lr) * (SQP * 2)
                                          + (k0 + 8 * hl) * 2));
                    bF[2 * nt2][0]     = r0;
                    bF[2 * nt2 + 1][0] = r1;
                    bF[2 * nt2][1]     = r2;
                    bF[2 * nt2 + 1][1] = r3;
                }
                #pragma unroll
                for (int nt = 0; nt < 4; nt++)
                    MMA16816(acc4[nt], aF, bF[nt]);
            }
        }

        // Store S transposed: PsT[key][query] (conflict-free scalar stores)
        {
            const int srow = wm + (lane >> 2);
            #pragma unroll
            for (int nt = 0; nt < 4; nt++) {
                const int scol = wn + nt * 8 + (lane & 3) * 2;
                PsT[scol * PP + srow]           = acc4[nt][0];
                PsT[(scol + 1) * PP + srow]     = acc4[nt][1];
                PsT[scol * PP + srow + 8]       = acc4[nt][2];
                PsT[(scol + 1) * PP + srow + 8] = acc4[nt][3];
            }
        }
        __syncthreads();   // S visible

        // Each thread reads its s[4][4] (qrows r*4.., kcols c*4..)
        float s[4][4];
        #pragma unroll
        for (int j = 0; j < 4; j++) {
            float4 v = *(const float4*)&PsT[(c * 4 + j) * PP + r * 4];
            s[0][j] = v.x; s[1][j] = v.y; s[2][j] = v.z; s[3][j] = v.w;
        }
        __syncthreads();   // all S reads done before P overwrites PsT

        // Mask + online softmax (unchanged)
        const int mok[4] = {mk4.x, mk4.y, mk4.z, mk4.w};
        float scl[4];
        #pragma unroll
        for (int i = 0; i < 4; i++) {
            const int qi = q0 + r * 4 + i;
            #pragma unroll
            for (int j = 0; j < 4; j++) {
                const int kj = kb + c * 4 + j;
                bool ok = (kj <= qi) && (kj > qi - WINDOW) && (mok[j] > 0);
                if (!ok) s[i][j] = -FLT_MAX;
            }
            float mx = fmaxf(fmaxf(s[i][0], s[i][1]), fmaxf(s[i][2], s[i][3]));
            #pragma unroll
            for (int w = 1; w <= 8; w <<= 1)
                mx = fmaxf(mx, __shfl_xor_sync(0xffffffffu, mx, w));

            float mnew = fmaxf(m[i], mx);
            scl[i] = __expf(m[i] - mnew);
            m[i] = mnew;

            float sum = 0.0f;
            #pragma unroll
            for (int j = 0; j < 4; j++) {
                float p = (s[i][j] > -1e37f) ? __expf(s[i][j] - mnew) : 0.0f;
                s[i][j] = p;
                sum += p;
            }
            #pragma unroll
            for (int w = 1; w <= 8; w <<= 1)
                sum += __shfl_xor_sync(0xffffffffu, sum, w);

            l[i] = l[i] * scl[i] + sum;
            #pragma unroll
            for (int dd = 0; dd < 8; dd++) o[i][dd] *= scl[i];
        }

        // Stage P transposed + rotated (pitch PP)
        #pragma unroll
        for (int j = 0; j < 4; j++) {
            int row  = c * 4 + j;
            int wcol = (4 * r + 4 * c) & 63;
            *(float4*)&PsT[row * PP + wcol] =
                make_float4(s[0][j], s[1][j], s[2][j], s[3][j]);
        }
        __syncthreads();

        // O += P @ V (unchanged)
        #pragma unroll 8
        for (int j = 0; j < BKC; j++) {
            int wcol = (4 * r + 4 * (j >> 2)) & 63;
            float4 p4 = *(const float4*)&PsT[j * PP + wcol];
            float4 va = *(const float4*)&Vs[j * 128 + c * 8];
            float4 vb = *(const float4*)&Vs[j * 128 + c * 8 + 4];
            const float pv[4] = {p4.x, p4.y, p4.z, p4.w};
            const float vv[8] = {va.x, va.y, va.z, va.w, vb.x, vb.y, vb.z, vb.w};
            #pragma unroll
            for (int i = 0; i < 4; i++)
                #pragma unroll
                for (int dd = 0; dd < 8; dd++)
                    o[i][dd] = fmaf(pv[i], vv[dd], o[i][dd]);
        }
    }

    // Normalize + store (tf32-rounded for the Wo tf32 gemm)
    #pragma unroll
    for (int i = 0; i < 4; i++) {
        const int row = q0 + r * 4 + i;
        const float inv = 1.0f / l[i];
        const long base = ((long)(b * SS + row)) * DD + h * HDIM + c * 8;
        float out[8];
        #pragma unroll
        for (int dd = 0; dd < 8; dd++) out[dd] = rna_tf32(o[i][dd] * inv);
        *(float4*)(O + base)     = make_float4(out[0], out[1], out[2], out[3]);
        *(float4*)(O + base + 4) = make_float4(out[4], out[5], out[6], out[7]);
    }
}

// ---------------------------------------------------------------------------
// Launch — QK bf16x3 gemm in slot 4 (profile target).
// ---------------------------------------------------------------------------
extern "C" void kernel_launch(void* const* d_in, const int* in_sizes, int n_in,
                              void* d_out, int out_size)
{
    const float* hs    = (const float*)d_in[0];
    const int*   amask = (const int*)  d_in[1];
    const float* Wq    = (const float*)d_in[2];
    const float* Wk    = (const float*)d_in[3];
    const float* Wv    = (const float*)d_in[4];
    const float* Wo    = (const float*)d_in[5];
    const float* bo    = (const float*)d_in[6];
    float*       out   = (float*)d_out;

    float *qkv, *ao, *wT;
    __nv_bfloat16 *ahi, *alo, *whi, *wlo;
    cudaGetSymbolAddress((void**)&qkv, g_qkv);
    cudaGetSymbolAddress((void**)&ao,  g_ao);
    cudaGetSymbolAddress((void**)&ahi, g_ahi);
    cudaGetSymbolAddress((void**)&alo, g_alo);
    cudaGetSymbolAddress((void**)&whi, g_whi);
    cudaGetSymbolAddress((void**)&wlo, g_wlo);
    cudaGetSymbolAddress((void**)&wT,  g_wT);

    cudaFuncSetAttribute(gemm_bf16x3_kernel,
                         cudaFuncAttributeMaxDynamicSharedMemorySize, GSMEM_TOTAL);
    cudaFuncSetAttribute(gemm_tf32_kernel,
                         cudaFuncAttributeMaxDynamicSharedMemorySize, TSMEM_TOTAL);
    cudaFuncSetAttribute(attn_local_kernel,
                         cudaFuncAttributeMaxDynamicSharedMemorySize, ATT_SMEM_BYTES);

    const int n4 = MROWS * DD / 4;

    // (1) hs -> bf16 hi/lo + tf32-rounded fp32 (in g_ao)
    split3_kernel<<<(n4 + 255) / 256, 256>>>(hs, ahi, alo, ao, n4);

    // (2) all weight prep in one launch
    dim3 wgrid(DD / 32, DD / 32, 4);
    wprep_kernel<<<wgrid, 256>>>(Wq, Wk, Wv, Wo, whi, wlo, wT);

    // (3) V GEMM (single-pass tf32)
    dim3 tgrid(DD / 128, MROWS / 128);
    gemm_tf32_kernel<<<tgrid, 256, TSMEM_TOTAL>>>(ao, wT, nullptr, qkv + 2 * MD);

    // (4) fused QK GEMM (bf16x3)  <-- ncu capture slot
    dim3 qkgrid(2 * DD / 128, MROWS / 128);
    gemm_bf16x3_kernel<<<qkgrid, 256, GSMEM_TOTAL>>>(ahi, alo, whi, wlo, nullptr, qkv);

    // (5) attention (HMMA S, fixed pitch): overwrites g_ao
    dim3 attn_grid(SS / BQ, HH, BB);
    attn_local_kernel<<<attn_grid, 256, ATT_SMEM_BYTES>>>(
        qkv, qkv + MD, qkv + 2 * MD, amask, ao);

    // (6) output projection (single-pass tf32)
    gemm_tf32_kernel<<<tgrid, 256, TSMEM_TOTAL>>>(ao, wT + (long)DD * DD, bo, out);
}